// round 2
// baseline (speedup 1.0000x reference)
#include <cuda_runtime.h>
#include <cuda_bf16.h>

// Bilateral filter: B=8, C=3, H=W=512, K=5, sigma_s=2.0, sigma_r=0.1
// w(i,j) = spatial(i,j) * exp(-(n-c)^2 * 50)
//        = exp2( log2(spatial) - ((n-c)*C1)^2 ),  C1 = sqrt(50*log2(e))
// out = sum(w*n) / sum(w)   (wsum >= 1 from center tap, no clip needed)
//
// R2: occupancy push. 2 pixels/thread, 512-thread CTAs, launch_bounds(512,3)
// -> 48 warps/SM (vs 32 before). MUFU (EX2) is the roofline; everything else
// is latency hiding.

#define HW 512
#define TILE 32
#define PAD 2
#define SMW (TILE + 2*PAD)   // 36
#define SMH (TILE + 2*PAD)   // 36

__device__ __forceinline__ float ex2_approx(float x) {
    float y;
    asm("ex2.approx.ftz.f32 %0, %1;" : "=f"(y) : "f"(x));
    return y;
}

__device__ __forceinline__ int reflect512(int g) {
    // valid for g in [-2, 513]
    g = (g < 0) ? -g : g;
    g = (g > 511) ? (1022 - g) : g;
    return g;
}

__global__ __launch_bounds__(512, 3)
void bilateral_kernel(const float* __restrict__ x,
                      const float* __restrict__ spatial,
                      float* __restrict__ out) {
    __shared__ float tile[SMH][SMW];
    __shared__ float ls[25];

    const int bx = blockIdx.x * TILE;
    const int by = blockIdx.y * TILE;
    const float* __restrict__ src = x   + (size_t)blockIdx.z * (HW * HW);
    float* __restrict__       dst = out + (size_t)blockIdx.z * (HW * HW);

    const int tid = threadIdx.y * 32 + threadIdx.x;

    if (tid < 25) {
        ls[tid] = __log2f(spatial[tid]);
    }

    // Cooperative tile load with reflect padding (36x36 = 1296 elems, 512 threads)
    #pragma unroll
    for (int idx = tid; idx < SMH * SMW; idx += 512) {
        int ly = idx / SMW;
        int lx = idx - ly * SMW;
        int gy = reflect512(by + ly - PAD);
        int gx = reflect512(bx + lx - PAD);
        tile[ly][lx] = src[gy * HW + gx];
    }
    __syncthreads();

    const float C1 = 8.4932165750422091f;  // sqrt(50 * log2(e))

    const int lx  = threadIdx.x;        // 0..31
    const int ly0 = threadIdx.y * 2;    // 0,2,...,30  (2 output rows per thread)

    float cC1[2], wsum[2], acc[2];
    #pragma unroll
    for (int k = 0; k < 2; k++) {
        float c = tile[ly0 + PAD + k][lx + PAD];
        cC1[k]  = c * C1;
        wsum[k] = 0.0f;
        acc[k]  = 0.0f;
    }

    #pragma unroll
    for (int j = 0; j < 5; j++) {
        // one 6-tall register column serves both pixels' 5-tall windows
        float v[6];
        #pragma unroll
        for (int r = 0; r < 6; r++) {
            v[r] = tile[ly0 + r][lx + j];
        }
        #pragma unroll
        for (int i = 0; i < 5; i++) {
            const float lsij = ls[i * 5 + j];
            #pragma unroll
            for (int k = 0; k < 2; k++) {
                float n = v[i + k];
                float d = fmaf(n, C1, -cC1[k]);          // FFMA-imm (rt=1)
                float w = ex2_approx(fmaf(d, -d, lsij)); // FFMA + MUFU.EX2
                wsum[k] += w;
                acc[k]   = fmaf(w, n, acc[k]);
            }
        }
    }

    #pragma unroll
    for (int k = 0; k < 2; k++) {
        int gy = by + ly0 + k;
        int gx = bx + lx;
        dst[gy * HW + gx] = __fdividef(acc[k], wsum[k]);
    }
}

extern "C" void kernel_launch(void* const* d_in, const int* in_sizes, int n_in,
                              void* d_out, int out_size) {
    const float* x       = (const float*)d_in[0];  // (8,3,512,512)
    const float* spatial = (const float*)d_in[1];  // (5,5)
    float* out           = (float*)d_out;

    dim3 block(32, 16);
    dim3 grid(HW / TILE, HW / TILE, 24);  // 16 x 16 x (B*C)
    bilateral_kernel<<<grid, block>>>(x, spatial, out);
}

// round 3
// speedup vs baseline: 1.0449x; 1.0449x over previous
#include <cuda_runtime.h>
#include <cuda_bf16.h>

// Bilateral filter: B=8, C=3, H=W=512, K=5, sigma_s=2.0, sigma_r=0.1
//
// R3: pairwise weight sharing. w(p,q) = spatial(d)*exp(-50(xp-xq)^2) is
// symmetric, so one EX2 serves both pixels' sums when one thread owns both.
// 4x4 pixel patch per thread -> 294 unique EX2 per 16 px (18.4/px) + free
// center tap, vs 25/px naive. MUFU (EX2) is the measured roofline.
//
// w = exp2( log2(spatial) - ((xp-xq)*C1)^2 ),  C1 = sqrt(50*log2(e))

#define HW 512
#define TILE 64
#define SROW 68            // smem row stride in floats (68*4B = 272B = 17*16B)
#define C1F 8.4932165750422091f

__device__ __forceinline__ float ex2a(float v) {
    float y;
    asm("ex2.approx.ftz.f32 %0, %1;" : "=f"(y) : "f"(v));
    return y;
}

__device__ __forceinline__ int reflect512(int g) {
    g = (g < 0) ? -g : g;
    return (g > 511) ? (1022 - g) : g;
}

// ownership of a window-local coordinate (window is 8x8, owned core is 2..5)
#define OWN(rr,cc) ((rr) >= 2 && (rr) <= 5 && (cc) >= 2 && (cc) <= 5)

// one unordered pair: a=(ra,ca) value va, b=(rb,cb) value vb, offset (di,dj)=b-a.
// All index args are compile-time constants after unrolling.
#define PAIR(va, vb, ra, ca, rb, cb, di, dj) do {                              \
    const bool oa_ = OWN(ra, ca), ob_ = OWN(rb, cb);                           \
    if (oa_ || ob_) {                                                          \
        float d_ = (va) - (vb);                                                \
        float t_ = d_ * C1F;                                                   \
        float w_ = ex2a(fmaf(t_, -t_, ls[((di)+2)*5 + ((dj)+2)]));             \
        if (oa_) { const int ia_ = ((ra)-2)*4 + ((ca)-2);                      \
                   wsum[ia_] += w_; acc[ia_] = fmaf(w_, (vb), acc[ia_]); }     \
        if (ob_) { const int ib_ = ((rb)-2)*4 + ((cb)-2);                      \
                   wsum[ib_] += w_; acc[ib_] = fmaf(w_, (va), acc[ib_]); }     \
    }                                                                          \
} while (0)

__global__ __launch_bounds__(256, 3)
void bilateral_kernel(const float* __restrict__ x,
                      const float* __restrict__ spatial,
                      float* __restrict__ out) {
    __shared__ float tile[68 * SROW];
    __shared__ float ls[25];
    __shared__ float scen;

    const int bx = blockIdx.x * TILE;
    const int by = blockIdx.y * TILE;
    const float* __restrict__ src = x   + (size_t)blockIdx.z * (HW * HW);
    float* __restrict__       dst = out + (size_t)blockIdx.z * (HW * HW);

    const int tx  = threadIdx.x;         // 0..15
    const int ty  = threadIdx.y;         // 0..15
    const int tid = ty * 16 + tx;

    if (tid < 25) ls[tid] = __log2f(spatial[tid]);
    if (tid == 25) scen = spatial[12];   // exp(0)*spatial_center

    // cooperative 68x68 tile load with reflect padding
    for (int i = tid; i < 68 * 68; i += 256) {
        int r = i / 68;
        int c = i - r * 68;
        tile[r * SROW + c] = src[reflect512(by + r - 2) * HW +
                                 reflect512(bx + c - 2)];
    }
    __syncthreads();

    const int R0 = 4 * ty;   // smem row of window origin
    const int C0 = 4 * tx;   // smem col of window origin
    const float sc = scen;

    float wsum[16], acc[16];
    #pragma unroll
    for (int i = 0; i < 16; i++) { wsum[i] = 0.0f; acc[i] = 0.0f; }

    float rows[3][8];   // rolling 3-row window buffer (all indices constant)

    #pragma unroll
    for (int r = 0; r < 8; r++) {
        const int cr = r % 3;

        // load window row r: cols C0..C0+7, two aligned float4
        {
            float4 a = *(const float4*)&tile[(R0 + r) * SROW + C0];
            float4 b = *(const float4*)&tile[(R0 + r) * SROW + C0 + 4];
            rows[cr][0] = a.x; rows[cr][1] = a.y;
            rows[cr][2] = a.z; rows[cr][3] = a.w;
            rows[cr][4] = b.x; rows[cr][5] = b.y;
            rows[cr][6] = b.z; rows[cr][7] = b.w;
        }

        // ---- center taps (offset (0,0)): weight == spatial center, no EX2
        if (r >= 2 && r <= 5) {
            #pragma unroll
            for (int c = 2; c <= 5; c++) {
                const int ia = (r - 2) * 4 + (c - 2);
                wsum[ia] += sc;
                acc[ia]   = fmaf(sc, rows[cr][c], acc[ia]);
            }
        }

        // ---- di=0 pairs (within row r) — need row owned
        if (r >= 2 && r <= 5) {
            #pragma unroll
            for (int c = 1; c <= 5; c++)       // dj = 1
                PAIR(rows[cr][c], rows[cr][c+1], r, c, r, c+1, 0, 1);
            #pragma unroll
            for (int c = 0; c <= 5; c++)       // dj = 2
                PAIR(rows[cr][c], rows[cr][c+2], r, c, r, c+2, 0, 2);
        }

        // ---- di=1 pairs: rows (r-1, r)
        if (r >= 1) {
            const int pr = (r - 1) % 3;
            #pragma unroll
            for (int dj = -2; dj <= 2; dj++) {
                #pragma unroll
                for (int c = 0; c < 8; c++) {
                    const int cb = c + dj;
                    if (cb < 0 || cb > 7) continue;
                    PAIR(rows[pr][c], rows[cr][cb], r-1, c, r, cb, 1, dj);
                }
            }
        }

        // ---- di=2 pairs: rows (r-2, r)
        if (r >= 2) {
            const int p2 = (r - 2) % 3;
            #pragma unroll
            for (int dj = -2; dj <= 2; dj++) {
                #pragma unroll
                for (int c = 0; c < 8; c++) {
                    const int cb = c + dj;
                    if (cb < 0 || cb > 7) continue;
                    PAIR(rows[p2][c], rows[cr][cb], r-2, c, r, cb, 2, dj);
                }
            }
        }
    }

    // ---- normalize + store (owned global rows by+R0+0..3, cols bx+C0+0..3)
    #pragma unroll
    for (int pr = 0; pr < 4; pr++) {
        float4 o;
        o.x = __fdividef(acc[pr*4 + 0], wsum[pr*4 + 0]);
        o.y = __fdividef(acc[pr*4 + 1], wsum[pr*4 + 1]);
        o.z = __fdividef(acc[pr*4 + 2], wsum[pr*4 + 2]);
        o.w = __fdividef(acc[pr*4 + 3], wsum[pr*4 + 3]);
        *(float4*)&dst[(by + R0 + pr) * HW + bx + C0] = o;
    }
}

extern "C" void kernel_launch(void* const* d_in, const int* in_sizes, int n_in,
                              void* d_out, int out_size) {
    const float* x       = (const float*)d_in[0];  // (8,3,512,512)
    const float* spatial = (const float*)d_in[1];  // (5,5)
    float* out           = (float*)d_out;

    dim3 block(16, 16);
    dim3 grid(HW / TILE, HW / TILE, 24);   // 8 x 8 x (B*C)
    bilateral_kernel<<<grid, block>>>(x, spatial, out);
}